// round 15
// baseline (speedup 1.0000x reference)
#include <cuda_runtime.h>
#include <math.h>

#define RIR_LENGTH 3968
#define PAD        40
#define BATCH      128
#define MAXO       15
#define GRID_TOT   29791
#define NIMG       4991          // |x|+|y|+|z| <= 15 lattice points
#define FSR        46.64723032f  // fp32(16000/343)
#define INV_PI     0.3183098862f

#define DIMAX      4007          // di <= 4007 <=> lowest tap bin <= 3967
#define BSH        2             // bucket = 4 delay-bins
#define NBUCK      1002          // ceil(4008/4)
#define MAXE       4992
#define EPAD       512           // sentinel pad (covers warp-max overrun + prefetch)
#define WMAX       64
#define SPMAX      32
#define TPB        1024
#define AITER      ((NIMG + TPB - 1) / TPB)   // 5

__device__ int g_xyz[NIMG + 32];

// closed-form prefix of octahedral layer sizes: P(m) = sum_{r=0}^{m} (2r^2+2r+1)
__device__ __forceinline__ int octP(int m) {
    return (m < 0) ? 0 : (m + 1) * (2 * m * m + 4 * m + 3) / 3;
}

// Deterministic, atomic-free compaction: lex-order rank of (ix,iy,iz).
__global__ void k_build_xyz() {
    int idx = blockIdx.x * blockDim.x + threadIdx.x;
    if (idx >= GRID_TOT) return;
    int iz  = idx / 961;
    int rem = idx - iz * 961;
    int iy  = rem / 31;
    int ix  = rem - iy * 31;
    ix -= MAXO; iy -= MAXO; iz -= MAXO;
    int ax = abs(ix), ay = abs(iy), az = abs(iz);
    if (ax + ay + az > MAXO) return;
    int Cx = (ix <= 0) ? octP(ix + 14) : 2736 + 2255 - octP(15 - ix);
    int r  = MAXO - ax;
    int Cy = (iy <= 0) ? (iy + r) * (iy + r)
                       : (r + 1) * (r + 1) + (iy - 1) * (2 * r - iy + 1);
    int slot = Cx + Cy + iz + (r - ay);
    g_xyz[slot] = (ix + 16) | ((iy + 16) << 8) | ((iz + 16) << 16);
}

// evaluate 4 entries (paired reciprocal) accumulating into A0/A1
#define EVAL4(E0, E1, E2, E3, JF, CJ, SJ, A0, A1) do {        \
    float x0_ = (JF) - (E0).x;                                \
    float x1_ = (JF) - (E1).x;                                \
    float t0_ = fmaf((CJ), (E0).z, (E0).y);                   \
    t0_ = fmaf((SJ), (E0).w, t0_);                            \
    t0_ = (fabsf(x0_) < 40.f) ? t0_ : 0.f;                    \
    float t1_ = fmaf((CJ), (E1).z, (E1).y);                   \
    t1_ = fmaf((SJ), (E1).w, t1_);                            \
    t1_ = (fabsf(x1_) < 40.f) ? t1_ : 0.f;                    \
    float r01_ = __fdividef(1.f, x0_ * x1_);                  \
    (A0) = fmaf(fmaf(t0_, x1_, t1_ * x0_), r01_, (A0));       \
    float x2_ = (JF) - (E2).x;                                \
    float x3_ = (JF) - (E3).x;                                \
    float t2_ = fmaf((CJ), (E2).z, (E2).y);                   \
    t2_ = fmaf((SJ), (E2).w, t2_);                            \
    t2_ = (fabsf(x2_) < 40.f) ? t2_ : 0.f;                    \
    float t3_ = fmaf((CJ), (E3).z, (E3).y);                   \
    t3_ = fmaf((SJ), (E3).w, t3_);                            \
    t3_ = (fabsf(x3_) < 40.f) ? t3_ : 0.f;                    \
    float r23_ = __fdividef(1.f, x2_ * x3_);                  \
    (A1) = fmaf(fmaf(t2_, x3_, t3_ * x2_), r23_, (A1));       \
} while (0)

// ---------------------------------------------------------------------------
__global__ __launch_bounds__(TPB) void k_all(const float* __restrict__ inp,
                                             float* __restrict__ out) {
    extern __shared__ __align__(16) char dynsm[];
    float4* sEnt   = (float4*)dynsm;                                     // [MAXE+EPAD]
    float2* sCache = (float2*)(dynsm + (MAXE + EPAD) * sizeof(float4));  // [MAXE]

    __shared__ float  sPW[16], sPL[9], sPH[9], sGeo[9];
    __shared__ float2 sCS[80];
    __shared__ int    hist[NBUCK], base[NBUCK + 1], cur[NBUCK];
    __shared__ int    segbase[33];
    __shared__ int    s_nsp, s_nwr;
    __shared__ int    s_spk_i[SPMAX];
    __shared__ float  s_spk_a[SPMAX];
    __shared__ float4 s_wrap[WMAX * 2];

    const int b   = blockIdx.x;
    const int tid = threadIdx.x;

    for (int k = tid; k < NBUCK; k += TPB) hist[k] = 0;
    if (tid < 80) {
        float c, s;
        sincospif((float)tid * 0.025f, &s, &c);
        sCS[tid] = make_float2(c, s);
    }
    if (tid == 0) {
        s_nsp = 0; s_nwr = 0;
        const float* r = inp + b * 12;
        float rx = r[0], ry = r[1], rz = r[2];
        sGeo[0] = rx;                  sGeo[1] = ry;                  sGeo[2] = rz;
        sGeo[3] = __fmul_rn(r[3], rx); sGeo[4] = __fmul_rn(r[4], ry); sGeo[5] = __fmul_rn(r[5], rz);
        sGeo[6] = __fmul_rn(r[6], rx); sGeo[7] = __fmul_rn(r[7], ry); sGeo[8] = __fmul_rn(r[8], rz);
        float aw  = __fadd_rn(__fmul_rn(r[9],  0.84f), 0.01f);
        float a4  = __fadd_rn(__fmul_rn(r[10], 0.84f), 0.01f);
        float a5  = __fadd_rn(__fmul_rn(r[11], 0.84f), 0.01f);
        double trw = sqrt(1.0 - (double)aw);
        double tr4 = sqrt(1.0 - (double)a4);
        double tr5 = sqrt(1.0 - (double)a5);
        double p = 1.0;
        for (int e = 0; e < 16; e++) { sPW[e] = (float)p; p *= trw; }
        p = 1.0;
        for (int e = 0; e < 9;  e++) { sPL[e] = (float)p; p *= tr4; }
        p = 1.0;
        for (int e = 0; e < 9;  e++) { sPH[e] = (float)p; p *= tr5; }
        // toa
        float dx = __fsub_rn(__fmul_rn(r[3], rx), __fmul_rn(r[6], rx));
        float dy = __fsub_rn(__fmul_rn(r[4], ry), __fmul_rn(r[7], ry));
        float dz = __fsub_rn(__fmul_rn(r[5], rz), __fmul_rn(r[8], rz));
        float ssq = __fadd_rn(__fadd_rn(__fmul_rn(dx, dx), __fmul_rn(dy, dy)),
                              __fmul_rn(dz, dz));
        out[BATCH * RIR_LENGTH + b] =
            __fadd_rn((float)PAD, __fmul_rn(__fsqrt_rn(ssq), FSR));
    }
    __syncthreads();

    const float d0 = sGeo[0], d1 = sGeo[1], d2 = sGeo[2];
    const float m0 = sGeo[3], m1 = sGeo[4], m2 = sGeo[5];
    const float s0 = sGeo[6], s1 = sGeo[7], s2v = sGeo[8];

    // ---- phase A: per-image delay/amp + histogram ----
    #pragma unroll
    for (int it = 0; it < AITER; it++) {
        int i = it * TPB + tid;
        if (i >= NIMG) break;
        int pk = g_xyz[i];
        int ix = (pk & 255) - 16;
        int iy = ((pk >> 8) & 255) - 16;
        int iz = (pk >> 16) - 16;
        float img0 = (ix & 1) ? __fsub_rn(__fmul_rn(d0, (float)(ix + 1)), s0)
                              : __fadd_rn(__fmul_rn(d0, (float)ix), s0);
        float img1 = (iy & 1) ? __fsub_rn(__fmul_rn(d1, (float)(iy + 1)), s1)
                              : __fadd_rn(__fmul_rn(d1, (float)iy), s1);
        float img2 = (iz & 1) ? __fsub_rn(__fmul_rn(d2, (float)(iz + 1)), s2v)
                              : __fadd_rn(__fmul_rn(d2, (float)iz), s2v);
        float e0 = __fsub_rn(img0, m0);
        float e1 = __fsub_rn(img1, m1);
        float e2 = __fsub_rn(img2, m2);
        float ssq = __fadd_rn(__fadd_rn(__fmul_rn(e0, e0), __fmul_rn(e1, e1)),
                              __fmul_rn(e2, e2));
        float dist  = __fsqrt_rn(ssq);
        float delay = __fmul_rn(dist, FSR);
        float dif   = ceilf(delay);
        int   di    = (int)dif;
        float amp   = -1.0f;
        if (di <= DIMAX) {
            int axy  = abs(ix) + abs(iy);
            int elo2 = (iz >= 0) ? (iz >> 1)       : ((-iz + 1) >> 1);
            int ehi2 = (iz >= 0) ? ((iz + 1) >> 1) : ((-iz) >> 1);
            float att = sPW[axy] * sPL[elo2] * sPH[ehi2];
            amp = __fdiv_rn(att, dist);
            if (__fsub_rn(dif, delay) != 0.0f)
                atomicAdd(&hist[di >> BSH], 1);
        }
        sCache[i] = make_float2(delay, amp);
    }
    __syncthreads();

    // ---- two-level prefix scan over NBUCK buckets (32 segments of 32) ----
    if (tid < 32) {
        int s = 0;
        int q0 = tid * 32;
        #pragma unroll
        for (int q = 0; q < 32; q++) {
            int k = q0 + q;
            if (k < NBUCK) s += hist[k];
        }
        int x = s;
        #pragma unroll
        for (int d = 1; d < 32; d <<= 1) {
            int v = __shfl_up_sync(0xffffffffu, x, d);
            if (tid >= d) x += v;
        }
        segbase[tid] = x - s;
        if (tid == 31) segbase[32] = x;
    }
    __syncthreads();
    for (int k = tid; k < NBUCK; k += TPB) {
        int s = segbase[k >> 5];
        for (int q = k & ~31; q < k; q++) s += hist[q];
        base[k] = s;
        cur[k]  = s;
    }
    if (tid == 0) base[NBUCK] = segbase[32];
    __syncthreads();

    // ---- phase B: finalize entries (pre-scaled by a2) ----
    #pragma unroll
    for (int it = 0; it < AITER; it++) {
        int c = it * TPB + tid;
        if (c >= NIMG) break;
        float2 E = sCache[c];
        float delay = E.x, amp = E.y;
        if (amp < 0.0f) continue;              // culled (di > DIMAX)
        float dif = ceilf(delay);
        int   di  = (int)dif;
        float frac = __fsub_rn(dif, delay);
        if (frac == 0.0f) {                    // pure spike: sinc peak only
            if (di < RIR_LENGTH) {
                int sp = atomicAdd(&s_nsp, 1);
                if (sp < SPMAX) { s_spk_i[sp] = di; s_spk_a[sp] = amp; }
            }
            continue;
        }
        float a2 = 0.5f * INV_PI * amp * sinpif(frac);
        if (di & 1) a2 = -a2;                  // (-1)^di
        int dm = di % 80;
        float cD, sD;
        sincospif(((float)dm - frac) * 0.025f, &sD, &cD);
        int slot = atomicAdd(&cur[di >> BSH], 1);
        sEnt[slot] = make_float4(delay, a2, a2 * cD, a2 * sD);
        if (di < PAD) {                        // near-field: JAX wrap duplicate
            int w = atomicAdd(&s_nwr, 1);
            if (w < WMAX) {
                int dm2 = (dm + 48) % 80;      // (di + 3968) % 80
                float cW, sW;
                sincospif(((float)dm2 - frac) * 0.025f, &sW, &cW);
                s_wrap[2 * w + 0] = make_float4((float)(di + RIR_LENGTH), frac, a2, 0.f);
                s_wrap[2 * w + 1] = make_float4(cW, sW, 0.f, 0.f);
            }
        }
    }
    __syncthreads();

    // sentinel pad: overruns/prefetch read delay=1e9, coeffs=0 -> contribute 0
    {
        int ntot = base[NBUCK];
        for (int k = tid; k < EPAD; k += TPB)
            sEnt[ntot + k] = make_float4(1e9f, 0.f, 0.f, 0.f);
    }
    __syncthreads();

    // ---- phase D: gather; pipelined loop unrolled x2, alternating buffers ----
    int nsp = min(s_nsp, SPMAX);
    int nwr = min(s_nwr, WMAX);
    float* orir = out + b * RIR_LENGTH;

    #pragma unroll
    for (int m = 0; m < 4; m++) {
        int j      = m * TPB + tid;
        int wstart = m * TPB + (tid & ~31);
        bool act   = (j < RIR_LENGTH);         // warp-uniform (3968 % 32 == 0)

        int g8 = m * TPB + (tid & ~7);         // group base bin (8-bin window)
        float jf = (float)j;
        int jm = j % 80;
        float2 cs = sCS[jm];
        float cj = cs.x, sj = cs.y;
        float onej = (jm & 1) ? -1.f : 1.f;

        int lob = (g8 - 39) >> BSH; if (lob < 0) lob = 0;
        int hib = (g8 + 47) >> BSH; if (hib > NBUCK - 1) hib = NBUCK - 1;
        int elo = base[lob];
        int cnt = act ? (base[hib + 1] - elo) : 0;
        int mc  = __reduce_max_sync(0xffffffffu, cnt);

        const float4* p = sEnt + elo;
        float a0 = 0.f, a1 = 0.f;

        // software-pipelined, unrolled x2 with alternating buffers (no copies)
        float4 c0 = p[0], c1 = p[1], c2 = p[2], c3 = p[3];
        float4 n0, n1, n2, n3;
        int it = 0;
        for (; it + 8 <= mc; it += 8) {
            n0 = p[it + 4]; n1 = p[it + 5]; n2 = p[it + 6]; n3 = p[it + 7];
            EVAL4(c0, c1, c2, c3, jf, cj, sj, a0, a1);
            c0 = p[it + 8]; c1 = p[it + 9]; c2 = p[it + 10]; c3 = p[it + 11];
            EVAL4(n0, n1, n2, n3, jf, cj, sj, a0, a1);
        }
        if (it + 4 <= mc) {                    // mid remainder: c* already loaded
            EVAL4(c0, c1, c2, c3, jf, cj, sj, a0, a1);
            it += 4;
        }
        for (; it < mc; it++) {                // scalar tail
            float4 E0 = p[it];
            float x = jf - E0.x;
            float t = fmaf(cj, E0.z, E0.y);
            t = fmaf(sj, E0.w, t);
            t = (fabsf(x) < 40.f) ? t : 0.f;
            a0 = fmaf(t, __fdividef(1.f, x), a0);
        }
        float acc = a0 + a1;

        // wrapped near-field taps land only in bins [3928, 3967]
        if (act && wstart + 31 >= RIR_LENGTH - PAD) {
            for (int w = 0; w < nwr; w++) {
                float4 A = s_wrap[2 * w], B = s_wrap[2 * w + 1];
                float x = (jf - A.x) + A.y;    // exact: int diff + frac
                float t = fmaf(cj, B.x, 1.f);
                t = fmaf(sj, B.y, t);
                t = (fabsf(x) < 40.f) ? t : 0.f;
                acc = fmaf(A.z * t, __fdividef(1.f, x), acc);
            }
        }
        acc *= onej;                           // deferred (-1)^j
        // spikes (rare)
        for (int sp = 0; sp < nsp; sp++)
            if (s_spk_i[sp] == j) acc += s_spk_a[sp];

        if (act) orir[j] = acc;
    }
}

// ---------------------------------------------------------------------------
extern "C" void kernel_launch(void* const* d_in, const int* in_sizes, int n_in,
                              void* d_out, int out_size) {
    const float* inp = (const float*)d_in[0];
    float* out = (float*)d_out;

    const int dynbytes = (MAXE + EPAD) * (int)sizeof(float4)
                       + MAXE * (int)sizeof(float2);          // 128,000
    cudaFuncSetAttribute(k_all, cudaFuncAttributeMaxDynamicSharedMemorySize, dynbytes);
    k_build_xyz<<<(GRID_TOT + 255) / 256, 256>>>();
    k_all<<<BATCH, TPB, dynbytes>>>(inp, out);
}

// round 16
// speedup vs baseline: 1.0360x; 1.0360x over previous
#include <cuda_runtime.h>
#include <math.h>

#define RIR_LENGTH 3968
#define PAD        40
#define BATCH      128
#define MAXO       15
#define GRID_TOT   29791
#define NIMG       4991          // |x|+|y|+|z| <= 15 lattice points
#define FSR        46.64723032f  // fp32(16000/343)
#define INV_PI     0.3183098862f

#define DIMAX      4007          // di <= 4007 <=> lowest tap bin <= 3967
#define BSH        2             // bucket = 4 delay-bins
#define NBUCK      1002          // ceil(4008/4)
#define MAXE       4992
#define EPAD       512           // sentinel pad (covers warp-max overrun + prefetch)
#define WMAX       64
#define SPMAX      32
#define TPB        1024
#define NCHUNK     (RIR_LENGTH / 32)          // 124 chunks of 32 bins
#define AITER      ((NIMG + TPB - 1) / TPB)   // 5

__device__ int g_xyz[NIMG + 32];

// closed-form prefix of octahedral layer sizes: P(m) = sum_{r=0}^{m} (2r^2+2r+1)
__device__ __forceinline__ int octP(int m) {
    return (m < 0) ? 0 : (m + 1) * (2 * m * m + 4 * m + 3) / 3;
}

// Deterministic, atomic-free compaction: lex-order rank of (ix,iy,iz).
__global__ void k_build_xyz() {
    int idx = blockIdx.x * blockDim.x + threadIdx.x;
    if (idx >= GRID_TOT) return;
    int iz  = idx / 961;
    int rem = idx - iz * 961;
    int iy  = rem / 31;
    int ix  = rem - iy * 31;
    ix -= MAXO; iy -= MAXO; iz -= MAXO;
    int ax = abs(ix), ay = abs(iy), az = abs(iz);
    if (ax + ay + az > MAXO) return;
    int Cx = (ix <= 0) ? octP(ix + 14) : 2736 + 2255 - octP(15 - ix);
    int r  = MAXO - ax;
    int Cy = (iy <= 0) ? (iy + r) * (iy + r)
                       : (r + 1) * (r + 1) + (iy - 1) * (2 * r - iy + 1);
    int slot = Cx + Cy + iz + (r - ay);
    g_xyz[slot] = (ix + 16) | ((iy + 16) << 8) | ((iz + 16) << 16);
}

// ---------------------------------------------------------------------------
__global__ __launch_bounds__(TPB) void k_all(const float* __restrict__ inp,
                                             float* __restrict__ out) {
    extern __shared__ __align__(16) char dynsm[];
    float4* sEnt   = (float4*)dynsm;                                     // [MAXE+EPAD]
    float2* sCache = (float2*)(dynsm + (MAXE + EPAD) * sizeof(float4));  // [MAXE]

    __shared__ float  sPW[16], sPL[9], sPH[9], sGeo[9];
    __shared__ float2 sCS[80];
    __shared__ int    hist[NBUCK], base[NBUCK + 1], cur[NBUCK];
    __shared__ int    segbase[33];
    __shared__ int    s_nsp, s_nwr, s_work;
    __shared__ int    s_spk_i[SPMAX];
    __shared__ float  s_spk_a[SPMAX];
    __shared__ float4 s_wrap[WMAX * 2];

    const int b    = blockIdx.x;
    const int tid  = threadIdx.x;
    const int lane = tid & 31;

    for (int k = tid; k < NBUCK; k += TPB) hist[k] = 0;
    if (tid < 80) {
        float c, s;
        sincospif((float)tid * 0.025f, &s, &c);
        sCS[tid] = make_float2(c, s);
    }
    if (tid == 0) {
        s_nsp = 0; s_nwr = 0; s_work = 0;
        const float* r = inp + b * 12;
        float rx = r[0], ry = r[1], rz = r[2];
        sGeo[0] = rx;                  sGeo[1] = ry;                  sGeo[2] = rz;
        sGeo[3] = __fmul_rn(r[3], rx); sGeo[4] = __fmul_rn(r[4], ry); sGeo[5] = __fmul_rn(r[5], rz);
        sGeo[6] = __fmul_rn(r[6], rx); sGeo[7] = __fmul_rn(r[7], ry); sGeo[8] = __fmul_rn(r[8], rz);
        float aw  = __fadd_rn(__fmul_rn(r[9],  0.84f), 0.01f);
        float a4  = __fadd_rn(__fmul_rn(r[10], 0.84f), 0.01f);
        float a5  = __fadd_rn(__fmul_rn(r[11], 0.84f), 0.01f);
        double trw = sqrt(1.0 - (double)aw);
        double tr4 = sqrt(1.0 - (double)a4);
        double tr5 = sqrt(1.0 - (double)a5);
        double p = 1.0;
        for (int e = 0; e < 16; e++) { sPW[e] = (float)p; p *= trw; }
        p = 1.0;
        for (int e = 0; e < 9;  e++) { sPL[e] = (float)p; p *= tr4; }
        p = 1.0;
        for (int e = 0; e < 9;  e++) { sPH[e] = (float)p; p *= tr5; }
        // toa
        float dx = __fsub_rn(__fmul_rn(r[3], rx), __fmul_rn(r[6], rx));
        float dy = __fsub_rn(__fmul_rn(r[4], ry), __fmul_rn(r[7], ry));
        float dz = __fsub_rn(__fmul_rn(r[5], rz), __fmul_rn(r[8], rz));
        float ssq = __fadd_rn(__fadd_rn(__fmul_rn(dx, dx), __fmul_rn(dy, dy)),
                              __fmul_rn(dz, dz));
        out[BATCH * RIR_LENGTH + b] =
            __fadd_rn((float)PAD, __fmul_rn(__fsqrt_rn(ssq), FSR));
    }
    __syncthreads();

    const float d0 = sGeo[0], d1 = sGeo[1], d2 = sGeo[2];
    const float m0 = sGeo[3], m1 = sGeo[4], m2 = sGeo[5];
    const float s0 = sGeo[6], s1 = sGeo[7], s2v = sGeo[8];

    // ---- phase A: per-image delay/amp + histogram ----
    #pragma unroll
    for (int it = 0; it < AITER; it++) {
        int i = it * TPB + tid;
        if (i >= NIMG) break;
        int pk = g_xyz[i];
        int ix = (pk & 255) - 16;
        int iy = ((pk >> 8) & 255) - 16;
        int iz = (pk >> 16) - 16;
        float img0 = (ix & 1) ? __fsub_rn(__fmul_rn(d0, (float)(ix + 1)), s0)
                              : __fadd_rn(__fmul_rn(d0, (float)ix), s0);
        float img1 = (iy & 1) ? __fsub_rn(__fmul_rn(d1, (float)(iy + 1)), s1)
                              : __fadd_rn(__fmul_rn(d1, (float)iy), s1);
        float img2 = (iz & 1) ? __fsub_rn(__fmul_rn(d2, (float)(iz + 1)), s2v)
                              : __fadd_rn(__fmul_rn(d2, (float)iz), s2v);
        float e0 = __fsub_rn(img0, m0);
        float e1 = __fsub_rn(img1, m1);
        float e2 = __fsub_rn(img2, m2);
        float ssq = __fadd_rn(__fadd_rn(__fmul_rn(e0, e0), __fmul_rn(e1, e1)),
                              __fmul_rn(e2, e2));
        float dist  = __fsqrt_rn(ssq);
        float delay = __fmul_rn(dist, FSR);
        float dif   = ceilf(delay);
        int   di    = (int)dif;
        float amp   = -1.0f;
        if (di <= DIMAX) {
            int axy  = abs(ix) + abs(iy);
            int elo2 = (iz >= 0) ? (iz >> 1)       : ((-iz + 1) >> 1);
            int ehi2 = (iz >= 0) ? ((iz + 1) >> 1) : ((-iz) >> 1);
            float att = sPW[axy] * sPL[elo2] * sPH[ehi2];
            amp = __fdiv_rn(att, dist);
            if (__fsub_rn(dif, delay) != 0.0f)
                atomicAdd(&hist[di >> BSH], 1);
        }
        sCache[i] = make_float2(delay, amp);
    }
    __syncthreads();

    // ---- two-level prefix scan over NBUCK buckets (32 segments of 32) ----
    if (tid < 32) {
        int s = 0;
        int q0 = tid * 32;
        #pragma unroll
        for (int q = 0; q < 32; q++) {
            int k = q0 + q;
            if (k < NBUCK) s += hist[k];
        }
        int x = s;
        #pragma unroll
        for (int d = 1; d < 32; d <<= 1) {
            int v = __shfl_up_sync(0xffffffffu, x, d);
            if (tid >= d) x += v;
        }
        segbase[tid] = x - s;
        if (tid == 31) segbase[32] = x;
    }
    __syncthreads();
    for (int k = tid; k < NBUCK; k += TPB) {
        int s = segbase[k >> 5];
        for (int q = k & ~31; q < k; q++) s += hist[q];
        base[k] = s;
        cur[k]  = s;
    }
    if (tid == 0) base[NBUCK] = segbase[32];
    __syncthreads();

    // ---- phase B: finalize entries (pre-scaled by a2) ----
    #pragma unroll
    for (int it = 0; it < AITER; it++) {
        int c = it * TPB + tid;
        if (c >= NIMG) break;
        float2 E = sCache[c];
        float delay = E.x, amp = E.y;
        if (amp < 0.0f) continue;              // culled (di > DIMAX)
        float dif = ceilf(delay);
        int   di  = (int)dif;
        float frac = __fsub_rn(dif, delay);
        if (frac == 0.0f) {                    // pure spike: sinc peak only
            if (di < RIR_LENGTH) {
                int sp = atomicAdd(&s_nsp, 1);
                if (sp < SPMAX) { s_spk_i[sp] = di; s_spk_a[sp] = amp; }
            }
            continue;
        }
        float a2 = 0.5f * INV_PI * amp * sinpif(frac);
        if (di & 1) a2 = -a2;                  // (-1)^di
        int dm = di % 80;
        float cD, sD;
        sincospif(((float)dm - frac) * 0.025f, &sD, &cD);
        int slot = atomicAdd(&cur[di >> BSH], 1);
        sEnt[slot] = make_float4(delay, a2, a2 * cD, a2 * sD);
        if (di < PAD) {                        // near-field: JAX wrap duplicate
            int w = atomicAdd(&s_nwr, 1);
            if (w < WMAX) {
                int dm2 = (dm + 48) % 80;      // (di + 3968) % 80
                float cW, sW;
                sincospif(((float)dm2 - frac) * 0.025f, &sW, &cW);
                s_wrap[2 * w + 0] = make_float4((float)(di + RIR_LENGTH), frac, a2, 0.f);
                s_wrap[2 * w + 1] = make_float4(cW, sW, 0.f, 0.f);
            }
        }
    }
    __syncthreads();

    // sentinel pad: overruns/prefetch read delay=1e9, coeffs=0 -> contribute 0
    {
        int ntot = base[NBUCK];
        for (int k = tid; k < EPAD; k += TPB)
            sEnt[ntot + k] = make_float4(1e9f, 0.f, 0.f, 0.f);
    }
    __syncthreads();

    // ---- phase D: gather with dynamic 32-bin chunk scheduling ----
    int nsp = min(s_nsp, SPMAX);
    int nwr = min(s_nwr, WMAX);
    float* orir = out + b * RIR_LENGTH;

    for (;;) {
        int ch;
        if (lane == 0) ch = atomicAdd(&s_work, 1);
        ch = __shfl_sync(0xffffffffu, ch, 0);
        if (ch >= NCHUNK) break;

        int wstart = ch * 32;
        int j = wstart + lane;
        int g8 = j & ~7;                       // group base bin (8-bin window)
        float jf = (float)j;
        int jm = j % 80;
        float2 cs = sCS[jm];
        float cj = cs.x, sj = cs.y;
        float onej = (jm & 1) ? -1.f : 1.f;

        int lob = (g8 - 39) >> BSH; if (lob < 0) lob = 0;
        int hib = (g8 + 47) >> BSH; if (hib > NBUCK - 1) hib = NBUCK - 1;
        int elo = base[lob];
        int cnt = base[hib + 1] - elo;
        int mc  = __reduce_max_sync(0xffffffffu, cnt);

        const float4* p = sEnt + elo;
        float a0 = 0.f, a1 = 0.f;

        // software-pipelined double buffer (sentinel pad makes preload safe)
        float4 c0 = p[0], c1 = p[1], c2 = p[2], c3 = p[3];
        int it = 0;
        for (; it + 4 <= mc; it += 4) {
            float4 n0 = p[it + 4], n1 = p[it + 5], n2 = p[it + 6], n3 = p[it + 7];
            // pair (c0, c1): one reciprocal
            float x0 = jf - c0.x;
            float x1 = jf - c1.x;
            float t0 = fmaf(cj, c0.z, c0.y);
            t0 = fmaf(sj, c0.w, t0);
            t0 = (fabsf(x0) < 40.f) ? t0 : 0.f;
            float t1 = fmaf(cj, c1.z, c1.y);
            t1 = fmaf(sj, c1.w, t1);
            t1 = (fabsf(x1) < 40.f) ? t1 : 0.f;
            float r01 = __fdividef(1.f, x0 * x1);
            a0 = fmaf(fmaf(t0, x1, t1 * x0), r01, a0);
            // pair (c2, c3): one reciprocal
            float x2 = jf - c2.x;
            float x3 = jf - c3.x;
            float t2 = fmaf(cj, c2.z, c2.y);
            t2 = fmaf(sj, c2.w, t2);
            t2 = (fabsf(x2) < 40.f) ? t2 : 0.f;
            float t3 = fmaf(cj, c3.z, c3.y);
            t3 = fmaf(sj, c3.w, t3);
            t3 = (fabsf(x3) < 40.f) ? t3 : 0.f;
            float r23 = __fdividef(1.f, x2 * x3);
            a1 = fmaf(fmaf(t2, x3, t3 * x2), r23, a1);
            c0 = n0; c1 = n1; c2 = n2; c3 = n3;
        }
        for (; it < mc; it++) {
            float4 E0 = p[it];
            float x = jf - E0.x;
            float t = fmaf(cj, E0.z, E0.y);
            t = fmaf(sj, E0.w, t);
            t = (fabsf(x) < 40.f) ? t : 0.f;
            a0 = fmaf(t, __fdividef(1.f, x), a0);
        }
        float acc = a0 + a1;

        // wrapped near-field taps land only in bins [3928, 3967]
        if (wstart + 31 >= RIR_LENGTH - PAD) {
            for (int w = 0; w < nwr; w++) {
                float4 A = s_wrap[2 * w], B = s_wrap[2 * w + 1];
                float x = (jf - A.x) + A.y;    // exact: int diff + frac
                float t = fmaf(cj, B.x, 1.f);
                t = fmaf(sj, B.y, t);
                t = (fabsf(x) < 40.f) ? t : 0.f;
                acc = fmaf(A.z * t, __fdividef(1.f, x), acc);
            }
        }
        acc *= onej;                           // deferred (-1)^j
        // spikes (rare)
        for (int sp = 0; sp < nsp; sp++)
            if (s_spk_i[sp] == j) acc += s_spk_a[sp];

        orir[j] = acc;
    }
}

// ---------------------------------------------------------------------------
extern "C" void kernel_launch(void* const* d_in, const int* in_sizes, int n_in,
                              void* d_out, int out_size) {
    const float* inp = (const float*)d_in[0];
    float* out = (float*)d_out;

    const int dynbytes = (MAXE + EPAD) * (int)sizeof(float4)
                       + MAXE * (int)sizeof(float2);          // 128,000
    cudaFuncSetAttribute(k_all, cudaFuncAttributeMaxDynamicSharedMemorySize, dynbytes);
    k_build_xyz<<<(GRID_TOT + 255) / 256, 256>>>();
    k_all<<<BATCH, TPB, dynbytes>>>(inp, out);
}